// round 4
// baseline (speedup 1.0000x reference)
#include <cuda_runtime.h>
#include <math.h>

// Problem dimensions
#define Bc   2
#define Sc   1024
#define Dc   768
#define Hc   12
#define HDc  64
#define DFFc 3072
#define Mrows (Bc*Sc)          // 2048

// ---------------------------------------------------------------------------
// Scratch (allocation-free: __device__ globals)
// ---------------------------------------------------------------------------
__device__ float g_xln [Mrows*Dc];
__device__ float g_qkv [Mrows*3*Dc];
__device__ float g_att [Mrows*Dc];
__device__ float g_res1[Mrows*Dc];
__device__ float g_hln [Mrows*Dc];
__device__ float g_ff  [Mrows*DFFc];

// ---------------------------------------------------------------------------
// LayerNorm: one block per row of 768
// ---------------------------------------------------------------------------
__global__ __launch_bounds__(256) void ln_kernel(
    const float* __restrict__ x, const float* __restrict__ g,
    const float* __restrict__ b, float* __restrict__ y)
{
    __shared__ float red[16];
    int row = blockIdx.x;
    int t = threadIdx.x;
    const float* xr = x + (size_t)row * Dc;
    float v0 = xr[t], v1 = xr[t + 256], v2 = xr[t + 512];
    float s  = v0 + v1 + v2;
    float ss = v0*v0 + v1*v1 + v2*v2;
    #pragma unroll
    for (int o = 16; o > 0; o >>= 1) {
        s  += __shfl_xor_sync(0xffffffffu, s,  o);
        ss += __shfl_xor_sync(0xffffffffu, ss, o);
    }
    int w = t >> 5;
    if ((t & 31) == 0) { red[w] = s; red[8 + w] = ss; }
    __syncthreads();
    s = 0.f; ss = 0.f;
    #pragma unroll
    for (int i = 0; i < 8; i++) { s += red[i]; ss += red[8 + i]; }
    float mean = s * (1.0f / Dc);
    float var  = ss * (1.0f / Dc) - mean * mean;
    float inv  = rsqrtf(var + 1e-5f);
    float* yr = y + (size_t)row * Dc;
    yr[t]       = (v0 - mean) * inv * g[t]       + b[t];
    yr[t + 256] = (v1 - mean) * inv * g[t + 256] + b[t + 256];
    yr[t + 512] = (v2 - mean) * inv * g[t + 512] + b[t + 512];
}

// ---------------------------------------------------------------------------
// SGEMM: C[M,N] = A[M,K] * B[N,K]^T (+bias) (relu) (+res)
// 128x128 tile, BK=8, 256 threads, 8x8 per thread (split 4+4)
// ---------------------------------------------------------------------------
__global__ __launch_bounds__(256) void sgemm_kernel(
    const float* __restrict__ A, const float* __restrict__ B,
    const float* __restrict__ bias, const float* __restrict__ res,
    float* __restrict__ C, int M, int N, int K, int do_relu)
{
    __shared__ float As[8][128];
    __shared__ float Bs[8][128];

    int tid = threadIdx.x;
    int tx = tid & 15, ty = tid >> 4;
    int bm = blockIdx.y * 128, bn = blockIdx.x * 128;

    int lrow = tid >> 1;          // 0..127
    int lkq  = (tid & 1) * 4;     // 0 or 4
    const float* Ag = A + (size_t)(bm + lrow) * K + lkq;
    const float* Bg = B + (size_t)(bn + lrow) * K + lkq;

    float acc[8][8];
    #pragma unroll
    for (int i = 0; i < 8; i++)
        #pragma unroll
        for (int j = 0; j < 8; j++) acc[i][j] = 0.f;

    for (int k0 = 0; k0 < K; k0 += 8) {
        float4 av = *(const float4*)(Ag + k0);
        float4 bv = *(const float4*)(Bg + k0);
        __syncthreads();
        As[lkq + 0][lrow] = av.x; As[lkq + 1][lrow] = av.y;
        As[lkq + 2][lrow] = av.z; As[lkq + 3][lrow] = av.w;
        Bs[lkq + 0][lrow] = bv.x; Bs[lkq + 1][lrow] = bv.y;
        Bs[lkq + 2][lrow] = bv.z; Bs[lkq + 3][lrow] = bv.w;
        __syncthreads();
        #pragma unroll
        for (int kk = 0; kk < 8; kk++) {
            float4 a0 = *(const float4*)&As[kk][4 * ty];
            float4 a1 = *(const float4*)&As[kk][64 + 4 * ty];
            float4 b0 = *(const float4*)&Bs[kk][4 * tx];
            float4 b1 = *(const float4*)&Bs[kk][64 + 4 * tx];
            float a[8] = {a0.x, a0.y, a0.z, a0.w, a1.x, a1.y, a1.z, a1.w};
            float bb[8] = {b0.x, b0.y, b0.z, b0.w, b1.x, b1.y, b1.z, b1.w};
            #pragma unroll
            for (int i = 0; i < 8; i++)
                #pragma unroll
                for (int j = 0; j < 8; j++)
                    acc[i][j] = fmaf(a[i], bb[j], acc[i][j]);
        }
    }

    #pragma unroll
    for (int i = 0; i < 8; i++) {
        int r = bm + ((i < 4) ? (4 * ty + i) : (64 + 4 * ty + (i - 4)));
        #pragma unroll
        for (int half = 0; half < 2; half++) {
            int c0 = bn + half * 64 + 4 * tx;
            float4 v;
            v.x = acc[i][half * 4 + 0];
            v.y = acc[i][half * 4 + 1];
            v.z = acc[i][half * 4 + 2];
            v.w = acc[i][half * 4 + 3];
            if (bias) {
                v.x += bias[c0 + 0]; v.y += bias[c0 + 1];
                v.z += bias[c0 + 2]; v.w += bias[c0 + 3];
            }
            if (do_relu) {
                v.x = fmaxf(v.x, 0.f); v.y = fmaxf(v.y, 0.f);
                v.z = fmaxf(v.z, 0.f); v.w = fmaxf(v.w, 0.f);
            }
            if (res) {
                float4 rv = *(const float4*)(res + (size_t)r * N + c0);
                v.x += rv.x; v.y += rv.y; v.z += rv.z; v.w += rv.w;
            }
            *(float4*)(C + (size_t)r * N + c0) = v;
        }
    }
}

// ---------------------------------------------------------------------------
// Fused attention (flash-style): per (q-block of 64, b*h)
// logits = (Q K^T + rel_gather(Q A^T)) / 8, masked, online softmax, @ V
// Q/K/V read from packed qkv [B,S,3D]; out written to [B,S,D] layout.
// smem: QS[64*64] | KP[64*65] (K tile, reused for P) | VS[64*64] | RR[64*4]
// ---------------------------------------------------------------------------
#define ATT_SMEM_FLOATS (64*64 + 64*65 + 64*64 + 64*4)

__global__ __launch_bounds__(256) void attn_kernel(
    const float* __restrict__ qkv,          // [B,S,3D]
    const int* __restrict__ relm,           // [B,S,S]
    const unsigned char* __restrict__ mask, // [B,S] (bool)
    const float* __restrict__ relA,         // [3,64]
    float* __restrict__ out)                // [B,S,D]
{
    extern __shared__ float sm[];
    float* QS = sm;                 // 64*64
    float* KP = QS + 64 * 64;       // 64*65 (padded stride 65)
    float* VS = KP + 64 * 65;       // 64*64
    float* RR = VS + 64 * 64;       // 64*4

    int tid = threadIdx.x;
    int tx = tid & 15, ty = tid >> 4;
    int qb = blockIdx.x;            // 0..15
    int bh = blockIdx.y;            // 0..23
    int b = bh / Hc, h = bh % Hc;
    int q0 = qb * 64;

    const float* qbase = qkv + (size_t)(b * Sc) * (3 * Dc) + h * HDc;
    const float* kbase = qbase + Dc;
    const float* vbase = qbase + 2 * Dc;

    // Load Q tile (float4, stride-64 smem)
    {
        int col4 = (tid & 15) * 4;
        for (int r = tid >> 4; r < 64; r += 16) {
            float4 v = *(const float4*)(qbase + (size_t)(q0 + r) * (3 * Dc) + col4);
            *(float4*)&QS[r * 64 + col4] = v;
        }
    }
    __syncthreads();

    // rrel[q][c] = sum_d Q[q,d] * relA[c,d]  (c = 0..2)
    if (tid < 192) {
        int q = tid / 3, c = tid % 3;
        float s = 0.f;
        const float* arow = relA + c * HDc;
        #pragma unroll 8
        for (int d = 0; d < 64; d++) s += QS[q * 64 + d] * arow[d];
        RR[q * 4 + c] = s;
    }
    __syncthreads();

    float mrow[4], lrow[4], o[4][4];
    #pragma unroll
    for (int i = 0; i < 4; i++) {
        mrow[i] = -INFINITY; lrow[i] = 0.f;
        #pragma unroll
        for (int j = 0; j < 4; j++) o[i][j] = 0.f;
    }

    const int* rmrow = relm + ((size_t)b * Sc + q0) * Sc;
    const unsigned char* mkrow = mask + (size_t)b * Sc;

    for (int kb = 0; kb < Sc / 64; kb++) {
        int k0 = kb * 64;
        __syncthreads();  // prior P/V reads done before overwrite
        {
            int col4 = (tid & 15) * 4;
            for (int r = tid >> 4; r < 64; r += 16) {
                float4 kv = *(const float4*)(kbase + (size_t)(k0 + r) * (3 * Dc) + col4);
                KP[r * 65 + col4 + 0] = kv.x; KP[r * 65 + col4 + 1] = kv.y;
                KP[r * 65 + col4 + 2] = kv.z; KP[r * 65 + col4 + 3] = kv.w;
                float4 vv = *(const float4*)(vbase + (size_t)(k0 + r) * (3 * Dc) + col4);
                *(float4*)&VS[r * 64 + col4] = vv;
            }
        }
        __syncthreads();

        // S tile = Q K^T
        float s[4][4];
        #pragma unroll
        for (int i = 0; i < 4; i++)
            #pragma unroll
            for (int j = 0; j < 4; j++) s[i][j] = 0.f;
        #pragma unroll 4
        for (int d = 0; d < 64; d++) {
            float a0 = QS[(4 * ty + 0) * 64 + d];
            float a1 = QS[(4 * ty + 1) * 64 + d];
            float a2 = QS[(4 * ty + 2) * 64 + d];
            float a3 = QS[(4 * ty + 3) * 64 + d];
            float b0 = KP[(4 * tx + 0) * 65 + d];
            float b1 = KP[(4 * tx + 1) * 65 + d];
            float b2 = KP[(4 * tx + 2) * 65 + d];
            float b3 = KP[(4 * tx + 3) * 65 + d];
            s[0][0] = fmaf(a0, b0, s[0][0]); s[0][1] = fmaf(a0, b1, s[0][1]);
            s[0][2] = fmaf(a0, b2, s[0][2]); s[0][3] = fmaf(a0, b3, s[0][3]);
            s[1][0] = fmaf(a1, b0, s[1][0]); s[1][1] = fmaf(a1, b1, s[1][1]);
            s[1][2] = fmaf(a1, b2, s[1][2]); s[1][3] = fmaf(a1, b3, s[1][3]);
            s[2][0] = fmaf(a2, b0, s[2][0]); s[2][1] = fmaf(a2, b1, s[2][1]);
            s[2][2] = fmaf(a2, b2, s[2][2]); s[2][3] = fmaf(a2, b3, s[2][3]);
            s[3][0] = fmaf(a3, b0, s[3][0]); s[3][1] = fmaf(a3, b1, s[3][1]);
            s[3][2] = fmaf(a3, b2, s[3][2]); s[3][3] = fmaf(a3, b3, s[3][3]);
        }

        // + rel gather, scale, mask
        #pragma unroll
        for (int j = 0; j < 4; j++) {
            int kg = k0 + 4 * tx + j;
            unsigned char mk = mkrow[kg];
            #pragma unroll
            for (int i = 0; i < 4; i++) {
                int ql = 4 * ty + i;
                int idx = rmrow[(size_t)ql * Sc + kg] + 1;   // 0,1,2
                float val = (s[i][j] + RR[ql * 4 + idx]) * 0.125f;
                s[i][j] = mk ? -INFINITY : val;
            }
        }

        // online softmax (row groups of 16 lanes)
        #pragma unroll
        for (int i = 0; i < 4; i++) {
            float tm = fmaxf(fmaxf(s[i][0], s[i][1]), fmaxf(s[i][2], s[i][3]));
            #pragma unroll
            for (int off = 1; off < 16; off <<= 1)
                tm = fmaxf(tm, __shfl_xor_sync(0xffffffffu, tm, off));
            float nm = fmaxf(mrow[i], tm);
            if (nm == -INFINITY) continue;   // fully-masked so far: nothing to update
            float alpha = (mrow[i] == -INFINITY) ? 0.f : __expf(mrow[i] - nm);
            float rs = 0.f;
            #pragma unroll
            for (int j = 0; j < 4; j++) {
                s[i][j] = __expf(s[i][j] - nm);
                rs += s[i][j];
            }
            #pragma unroll
            for (int off = 1; off < 16; off <<= 1)
                rs += __shfl_xor_sync(0xffffffffu, rs, off);
            lrow[i] = lrow[i] * alpha + rs;
            #pragma unroll
            for (int j = 0; j < 4; j++) o[i][j] *= alpha;
            mrow[i] = nm;
        }

        __syncthreads();  // done reading K from KP
        #pragma unroll
        for (int i = 0; i < 4; i++)
            #pragma unroll
            for (int j = 0; j < 4; j++)
                KP[(4 * ty + i) * 65 + 4 * tx + j] = (mrow[i] == -INFINITY) ? 0.f : s[i][j];
        __syncthreads();

        // O += P @ V
        #pragma unroll 4
        for (int k = 0; k < 64; k++) {
            float4 vv = *(const float4*)&VS[k * 64 + 4 * tx];
            float p0 = KP[(4 * ty + 0) * 65 + k];
            float p1 = KP[(4 * ty + 1) * 65 + k];
            float p2 = KP[(4 * ty + 2) * 65 + k];
            float p3 = KP[(4 * ty + 3) * 65 + k];
            o[0][0] = fmaf(p0, vv.x, o[0][0]); o[0][1] = fmaf(p0, vv.y, o[0][1]);
            o[0][2] = fmaf(p0, vv.z, o[0][2]); o[0][3] = fmaf(p0, vv.w, o[0][3]);
            o[1][0] = fmaf(p1, vv.x, o[1][0]); o[1][1] = fmaf(p1, vv.y, o[1][1]);
            o[1][2] = fmaf(p1, vv.z, o[1][2]); o[1][3] = fmaf(p1, vv.w, o[1][3]);
            o[2][0] = fmaf(p2, vv.x, o[2][0]); o[2][1] = fmaf(p2, vv.y, o[2][1]);
            o[2][2] = fmaf(p2, vv.z, o[2][2]); o[2][3] = fmaf(p2, vv.w, o[2][3]);
            o[3][0] = fmaf(p3, vv.x, o[3][0]); o[3][1] = fmaf(p3, vv.y, o[3][1]);
            o[3][2] = fmaf(p3, vv.z, o[3][2]); o[3][3] = fmaf(p3, vv.w, o[3][3]);
        }
    }

    // finalize: divide by l and write to [B,S,D] at column h*64
    #pragma unroll
    for (int i = 0; i < 4; i++) {
        float inv = (lrow[i] > 0.f) ? (1.f / lrow[i]) : 0.f;
        int qg = q0 + 4 * ty + i;
        float4 v;
        v.x = o[i][0] * inv; v.y = o[i][1] * inv;
        v.z = o[i][2] * inv; v.w = o[i][3] * inv;
        *(float4*)(out + ((size_t)(b * Sc) + qg) * Dc + h * HDc + 4 * tx) = v;
    }
}

// ---------------------------------------------------------------------------
// Launcher
// ---------------------------------------------------------------------------
extern "C" void kernel_launch(void* const* d_in, const int* in_sizes, int n_in,
                              void* d_out, int out_size)
{
    const float*         inp   = (const float*)d_in[0];
    const unsigned char* mask  = (const unsigned char*)d_in[1];
    const int*           relm  = (const int*)d_in[2];
    const float*         qkv_w = (const float*)d_in[3];
    const float*         relA  = (const float*)d_in[4];
    const float*         o_w   = (const float*)d_in[5];
    const float*         w1    = (const float*)d_in[6];
    const float*         b1    = (const float*)d_in[7];
    const float*         w2    = (const float*)d_in[8];
    const float*         b2    = (const float*)d_in[9];
    const float*         ln1g  = (const float*)d_in[10];
    const float*         ln1b  = (const float*)d_in[11];
    const float*         ln2g  = (const float*)d_in[12];
    const float*         ln2b  = (const float*)d_in[13];
    float* out = (float*)d_out;

    float *p_xln, *p_qkv, *p_att, *p_res1, *p_hln, *p_ff;
    cudaGetSymbolAddress((void**)&p_xln,  g_xln);
    cudaGetSymbolAddress((void**)&p_qkv,  g_qkv);
    cudaGetSymbolAddress((void**)&p_att,  g_att);
    cudaGetSymbolAddress((void**)&p_res1, g_res1);
    cudaGetSymbolAddress((void**)&p_hln,  g_hln);
    cudaGetSymbolAddress((void**)&p_ff,   g_ff);

    cudaFuncSetAttribute(attn_kernel, cudaFuncAttributeMaxDynamicSharedMemorySize,
                         ATT_SMEM_FLOATS * (int)sizeof(float));

    // 1. LN1
    ln_kernel<<<Mrows, 256>>>(inp, ln1g, ln1b, p_xln);

    // 2. QKV = xln @ qkv_w^T       [2048 x 2304]
    sgemm_kernel<<<dim3(3 * Dc / 128, Mrows / 128), 256>>>(
        p_xln, qkv_w, nullptr, nullptr, p_qkv, Mrows, 3 * Dc, Dc, 0);

    // 3. Fused attention
    attn_kernel<<<dim3(Sc / 64, Bc * Hc), 256, ATT_SMEM_FLOATS * sizeof(float)>>>(
        p_qkv, relm, mask, relA, p_att);

    // 4. res1 = inp + att @ o_w^T  [2048 x 768]
    sgemm_kernel<<<dim3(Dc / 128, Mrows / 128), 256>>>(
        p_att, o_w, nullptr, inp, p_res1, Mrows, Dc, Dc, 0);

    // 5. LN2
    ln_kernel<<<Mrows, 256>>>(p_res1, ln2g, ln2b, p_hln);

    // 6. ff = relu(hln @ w1^T + b1)  [2048 x 3072]
    sgemm_kernel<<<dim3(DFFc / 128, Mrows / 128), 256>>>(
        p_hln, w1, b1, nullptr, p_ff, Mrows, DFFc, Dc, 1);

    // 7. out = res1 + ff @ w2^T + b2  [2048 x 768]
    sgemm_kernel<<<dim3(Dc / 128, Mrows / 128), 256>>>(
        p_ff, w2, b2, p_res1, out, Mrows, Dc, DFFc, 0);
}

// round 8
// speedup vs baseline: 1.1981x; 1.1981x over previous
#include <cuda_runtime.h>
#include <math.h>

// Problem dimensions
#define Bc   2
#define Sc   1024
#define Dc   768
#define Hc   12
#define HDc  64
#define DFFc 3072
#define Mrows (Bc*Sc)          // 2048

// ---------------------------------------------------------------------------
// Scratch (allocation-free: __device__ globals)
// ---------------------------------------------------------------------------
__device__ float g_xln [Mrows*Dc];
__device__ float g_qkv [Mrows*3*Dc];
__device__ float g_att [Mrows*Dc];
__device__ float g_res1[Mrows*Dc];
__device__ float g_hln [Mrows*Dc];
__device__ float g_ff  [Mrows*DFFc];

// ---------------------------------------------------------------------------
// LayerNorm: one block per row of 768
// ---------------------------------------------------------------------------
__global__ __launch_bounds__(256) void ln_kernel(
    const float* __restrict__ x, const float* __restrict__ g,
    const float* __restrict__ b, float* __restrict__ y)
{
    __shared__ float red[16];
    int row = blockIdx.x;
    int t = threadIdx.x;
    const float* xr = x + (size_t)row * Dc;
    float v0 = xr[t], v1 = xr[t + 256], v2 = xr[t + 512];
    float s  = v0 + v1 + v2;
    float ss = v0*v0 + v1*v1 + v2*v2;
    #pragma unroll
    for (int o = 16; o > 0; o >>= 1) {
        s  += __shfl_xor_sync(0xffffffffu, s,  o);
        ss += __shfl_xor_sync(0xffffffffu, ss, o);
    }
    int w = t >> 5;
    if ((t & 31) == 0) { red[w] = s; red[8 + w] = ss; }
    __syncthreads();
    s = 0.f; ss = 0.f;
    #pragma unroll
    for (int i = 0; i < 8; i++) { s += red[i]; ss += red[8 + i]; }
    float mean = s * (1.0f / Dc);
    float var  = ss * (1.0f / Dc) - mean * mean;
    float inv  = rsqrtf(var + 1e-5f);
    float* yr = y + (size_t)row * Dc;
    yr[t]       = (v0 - mean) * inv * g[t]       + b[t];
    yr[t + 256] = (v1 - mean) * inv * g[t + 256] + b[t + 256];
    yr[t + 512] = (v2 - mean) * inv * g[t + 512] + b[t + 512];
}

// ---------------------------------------------------------------------------
// SGEMM (double-buffered): C[M,N] = A[M,K]*B[N,K]^T (+bias)(relu)(+res)
// BN=128, BK=16, 256 threads. BM template: 128 (8x8/thread) or 64 (4x8).
// One __syncthreads per BK=16; ldg(next) -> compute(cur) -> sts(next).
// ---------------------------------------------------------------------------
template<int BM>
__global__ __launch_bounds__(256, 2) void sgemm_db(
    const float* __restrict__ A, const float* __restrict__ B,
    const float* __restrict__ bias, const float* __restrict__ res,
    float* __restrict__ C, int M, int N, int K, int do_relu)
{
    constexpr int BN = 128;
    constexpr int BK = 16;
    constexpr int TM = BM / 16;          // 8 or 4
    constexpr int AV = BM / 64;          // float4s per thread for A tile (2 or 1)

    __shared__ float As[2][BK][BM];
    __shared__ float Bs[2][BK][BN];

    int tid = threadIdx.x;
    int tx = tid & 15, ty = tid >> 4;
    int bm = blockIdx.y * BM, bn = blockIdx.x * BN;

    // Load mappings (A tile BM x 16, B tile 128 x 16)
    int arow, akq;
    if (BM == 128) { arow = tid >> 1; akq = (tid & 1) * 8; }
    else           { arow = tid >> 2; akq = (tid & 3) * 4; }
    int brow = tid >> 1, bkq = (tid & 1) * 8;

    const float* Ag = A + (size_t)(bm + arow) * K + akq;
    const float* Bg = B + (size_t)(bn + brow) * K + bkq;

    float4 areg[AV], breg[2];

    float acc[TM][8];
    #pragma unroll
    for (int i = 0; i < TM; i++)
        #pragma unroll
        for (int j = 0; j < 8; j++) acc[i][j] = 0.f;

    // prologue: load tile 0 into regs, store to buffer 0
    #pragma unroll
    for (int v = 0; v < AV; v++) areg[v] = *(const float4*)(Ag + 4 * v);
    breg[0] = *(const float4*)(Bg);
    breg[1] = *(const float4*)(Bg + 4);

    #pragma unroll
    for (int v = 0; v < AV; v++) {
        As[0][akq + 4*v + 0][arow] = areg[v].x;
        As[0][akq + 4*v + 1][arow] = areg[v].y;
        As[0][akq + 4*v + 2][arow] = areg[v].z;
        As[0][akq + 4*v + 3][arow] = areg[v].w;
    }
    #pragma unroll
    for (int v = 0; v < 2; v++) {
        Bs[0][bkq + 4*v + 0][brow] = breg[v].x;
        Bs[0][bkq + 4*v + 1][brow] = breg[v].y;
        Bs[0][bkq + 4*v + 2][brow] = breg[v].z;
        Bs[0][bkq + 4*v + 3][brow] = breg[v].w;
    }
    __syncthreads();

    int nt = K / BK;
    for (int kt = 0; kt < nt; kt++) {
        int cur = kt & 1;
        if (kt + 1 < nt) {
            const float* Ag2 = Ag + (size_t)(kt + 1) * BK;
            const float* Bg2 = Bg + (size_t)(kt + 1) * BK;
            #pragma unroll
            for (int v = 0; v < AV; v++) areg[v] = *(const float4*)(Ag2 + 4 * v);
            breg[0] = *(const float4*)(Bg2);
            breg[1] = *(const float4*)(Bg2 + 4);
        }

        #pragma unroll
        for (int kk = 0; kk < BK; kk++) {
            float a[TM], b[8];
            if (BM == 128) {
                float4 a0 = *(const float4*)&As[cur][kk][4 * ty];
                float4 a1 = *(const float4*)&As[cur][kk][64 + 4 * ty];
                a[0] = a0.x; a[1] = a0.y; a[2] = a0.z; a[3] = a0.w;
                a[4] = a1.x; a[5] = a1.y; a[6] = a1.z; a[7] = a1.w;
            } else {
                float4 a0 = *(const float4*)&As[cur][kk][4 * ty];
                a[0] = a0.x; a[1] = a0.y; a[2] = a0.z; a[3] = a0.w;
            }
            float4 b0 = *(const float4*)&Bs[cur][kk][4 * tx];
            float4 b1 = *(const float4*)&Bs[cur][kk][64 + 4 * tx];
            b[0] = b0.x; b[1] = b0.y; b[2] = b0.z; b[3] = b0.w;
            b[4] = b1.x; b[5] = b1.y; b[6] = b1.z; b[7] = b1.w;
            #pragma unroll
            for (int i = 0; i < TM; i++)
                #pragma unroll
                for (int j = 0; j < 8; j++)
                    acc[i][j] = fmaf(a[i], b[j], acc[i][j]);
        }

        if (kt + 1 < nt) {
            int nxt = cur ^ 1;
            #pragma unroll
            for (int v = 0; v < AV; v++) {
                As[nxt][akq + 4*v + 0][arow] = areg[v].x;
                As[nxt][akq + 4*v + 1][arow] = areg[v].y;
                As[nxt][akq + 4*v + 2][arow] = areg[v].z;
                As[nxt][akq + 4*v + 3][arow] = areg[v].w;
            }
            #pragma unroll
            for (int v = 0; v < 2; v++) {
                Bs[nxt][bkq + 4*v + 0][brow] = breg[v].x;
                Bs[nxt][bkq + 4*v + 1][brow] = breg[v].y;
                Bs[nxt][bkq + 4*v + 2][brow] = breg[v].z;
                Bs[nxt][bkq + 4*v + 3][brow] = breg[v].w;
            }
            __syncthreads();
        }
    }

    // Epilogue
    #pragma unroll
    for (int i = 0; i < TM; i++) {
        int r;
        if (BM == 128) r = bm + ((i < 4) ? (4 * ty + i) : (64 + 4 * ty + (i - 4)));
        else           r = bm + 4 * ty + i;
        #pragma unroll
        for (int half = 0; half < 2; half++) {
            int c0 = bn + half * 64 + 4 * tx;
            float4 v;
            v.x = acc[i][half * 4 + 0];
            v.y = acc[i][half * 4 + 1];
            v.z = acc[i][half * 4 + 2];
            v.w = acc[i][half * 4 + 3];
            if (bias) {
                v.x += bias[c0 + 0]; v.y += bias[c0 + 1];
                v.z += bias[c0 + 2]; v.w += bias[c0 + 3];
            }
            if (do_relu) {
                v.x = fmaxf(v.x, 0.f); v.y = fmaxf(v.y, 0.f);
                v.z = fmaxf(v.z, 0.f); v.w = fmaxf(v.w, 0.f);
            }
            if (res) {
                float4 rv = *(const float4*)(res + (size_t)r * N + c0);
                v.x += rv.x; v.y += rv.y; v.z += rv.z; v.w += rv.w;
            }
            *(float4*)(C + (size_t)r * N + c0) = v;
        }
    }
}

// ---------------------------------------------------------------------------
// Fused attention (flash-style): per (q-block of 64, b*h)
// ---------------------------------------------------------------------------
#define ATT_SMEM_FLOATS (64*64 + 64*65 + 64*64 + 64*4)

__global__ __launch_bounds__(256) void attn_kernel(
    const float* __restrict__ qkv,          // [B,S,3D]
    const int* __restrict__ relm,           // [B,S,S]
    const unsigned char* __restrict__ mask, // [B,S] (bool)
    const float* __restrict__ relA,         // [3,64]
    float* __restrict__ out)                // [B,S,D]
{
    extern __shared__ float sm[];
    float* QS = sm;                 // 64*64
    float* KP = QS + 64 * 64;       // 64*65 (padded stride 65)
    float* VS = KP + 64 * 65;       // 64*64
    float* RR = VS + 64 * 64;       // 64*4

    int tid = threadIdx.x;
    int tx = tid & 15, ty = tid >> 4;
    int qb = blockIdx.x;            // 0..15
    int bh = blockIdx.y;            // 0..23
    int b = bh / Hc, h = bh % Hc;
    int q0 = qb * 64;

    const float* qbase = qkv + (size_t)(b * Sc) * (3 * Dc) + h * HDc;
    const float* kbase = qbase + Dc;
    const float* vbase = qbase + 2 * Dc;

    {
        int col4 = (tid & 15) * 4;
        for (int r = tid >> 4; r < 64; r += 16) {
            float4 v = *(const float4*)(qbase + (size_t)(q0 + r) * (3 * Dc) + col4);
            *(float4*)&QS[r * 64 + col4] = v;
        }
    }
    __syncthreads();

    if (tid < 192) {
        int q = tid / 3, c = tid % 3;
        float s = 0.f;
        const float* arow = relA + c * HDc;
        #pragma unroll 8
        for (int d = 0; d < 64; d++) s += QS[q * 64 + d] * arow[d];
        RR[q * 4 + c] = s;
    }
    __syncthreads();

    float mrow[4], lrow[4], o[4][4];
    #pragma unroll
    for (int i = 0; i < 4; i++) {
        mrow[i] = -INFINITY; lrow[i] = 0.f;
        #pragma unroll
        for (int j = 0; j < 4; j++) o[i][j] = 0.f;
    }

    const int* rmrow = relm + ((size_t)b * Sc + q0) * Sc;
    const unsigned char* mkrow = mask + (size_t)b * Sc;

    for (int kb = 0; kb < Sc / 64; kb++) {
        int k0 = kb * 64;
        __syncthreads();
        {
            int col4 = (tid & 15) * 4;
            for (int r = tid >> 4; r < 64; r += 16) {
                float4 kv = *(const float4*)(kbase + (size_t)(k0 + r) * (3 * Dc) + col4);
                KP[r * 65 + col4 + 0] = kv.x; KP[r * 65 + col4 + 1] = kv.y;
                KP[r * 65 + col4 + 2] = kv.z; KP[r * 65 + col4 + 3] = kv.w;
                float4 vv = *(const float4*)(vbase + (size_t)(k0 + r) * (3 * Dc) + col4);
                *(float4*)&VS[r * 64 + col4] = vv;
            }
        }
        __syncthreads();

        float s[4][4];
        #pragma unroll
        for (int i = 0; i < 4; i++)
            #pragma unroll
            for (int j = 0; j < 4; j++) s[i][j] = 0.f;
        #pragma unroll 4
        for (int d = 0; d < 64; d++) {
            float a0 = QS[(4 * ty + 0) * 64 + d];
            float a1 = QS[(4 * ty + 1) * 64 + d];
            float a2 = QS[(4 * ty + 2) * 64 + d];
            float a3 = QS[(4 * ty + 3) * 64 + d];
            float b0 = KP[(4 * tx + 0) * 65 + d];
            float b1 = KP[(4 * tx + 1) * 65 + d];
            float b2 = KP[(4 * tx + 2) * 65 + d];
            float b3 = KP[(4 * tx + 3) * 65 + d];
            s[0][0] = fmaf(a0, b0, s[0][0]); s[0][1] = fmaf(a0, b1, s[0][1]);
            s[0][2] = fmaf(a0, b2, s[0][2]); s[0][3] = fmaf(a0, b3, s[0][3]);
            s[1][0] = fmaf(a1, b0, s[1][0]); s[1][1] = fmaf(a1, b1, s[1][1]);
            s[1][2] = fmaf(a1, b2, s[1][2]); s[1][3] = fmaf(a1, b3, s[1][3]);
            s[2][0] = fmaf(a2, b0, s[2][0]); s[2][1] = fmaf(a2, b1, s[2][1]);
            s[2][2] = fmaf(a2, b2, s[2][2]); s[2][3] = fmaf(a2, b3, s[2][3]);
            s[3][0] = fmaf(a3, b0, s[3][0]); s[3][1] = fmaf(a3, b1, s[3][1]);
            s[3][2] = fmaf(a3, b2, s[3][2]); s[3][3] = fmaf(a3, b3, s[3][3]);
        }

        #pragma unroll
        for (int j = 0; j < 4; j++) {
            int kg = k0 + 4 * tx + j;
            unsigned char mk = mkrow[kg];
            #pragma unroll
            for (int i = 0; i < 4; i++) {
                int ql = 4 * ty + i;
                int idx = rmrow[(size_t)ql * Sc + kg] + 1;   // 0,1,2
                float val = (s[i][j] + RR[ql * 4 + idx]) * 0.125f;
                s[i][j] = mk ? -INFINITY : val;
            }
        }

        #pragma unroll
        for (int i = 0; i < 4; i++) {
            float tm = fmaxf(fmaxf(s[i][0], s[i][1]), fmaxf(s[i][2], s[i][3]));
            #pragma unroll
            for (int off = 1; off < 16; off <<= 1)
                tm = fmaxf(tm, __shfl_xor_sync(0xffffffffu, tm, off));
            float nm = fmaxf(mrow[i], tm);
            if (nm == -INFINITY) continue;
            float alpha = (mrow[i] == -INFINITY) ? 0.f : __expf(mrow[i] - nm);
            float rs = 0.f;
            #pragma unroll
            for (int j = 0; j < 4; j++) {
                s[i][j] = __expf(s[i][j] - nm);
                rs += s[i][j];
            }
            #pragma unroll
            for (int off = 1; off < 16; off <<= 1)
                rs += __shfl_xor_sync(0xffffffffu, rs, off);
            lrow[i] = lrow[i] * alpha + rs;
            #pragma unroll
            for (int j = 0; j < 4; j++) o[i][j] *= alpha;
            mrow[i] = nm;
        }

        __syncthreads();
        #pragma unroll
        for (int i = 0; i < 4; i++)
            #pragma unroll
            for (int j = 0; j < 4; j++)
                KP[(4 * ty + i) * 65 + 4 * tx + j] = (mrow[i] == -INFINITY) ? 0.f : s[i][j];
        __syncthreads();

        #pragma unroll 4
        for (int k = 0; k < 64; k++) {
            float4 vv = *(const float4*)&VS[k * 64 + 4 * tx];
            float p0 = KP[(4 * ty + 0) * 65 + k];
            float p1 = KP[(4 * ty + 1) * 65 + k];
            float p2 = KP[(4 * ty + 2) * 65 + k];
            float p3 = KP[(4 * ty + 3) * 65 + k];
            o[0][0] = fmaf(p0, vv.x, o[0][0]); o[0][1] = fmaf(p0, vv.y, o[0][1]);
            o[0][2] = fmaf(p0, vv.z, o[0][2]); o[0][3] = fmaf(p0, vv.w, o[0][3]);
            o[1][0] = fmaf(p1, vv.x, o[1][0]); o[1][1] = fmaf(p1, vv.y, o[1][1]);
            o[1][2] = fmaf(p1, vv.z, o[1][2]); o[1][3] = fmaf(p1, vv.w, o[1][3]);
            o[2][0] = fmaf(p2, vv.x, o[2][0]); o[2][1] = fmaf(p2, vv.y, o[2][1]);
            o[2][2] = fmaf(p2, vv.z, o[2][2]); o[2][3] = fmaf(p2, vv.w, o[2][3]);
            o[3][0] = fmaf(p3, vv.x, o[3][0]); o[3][1] = fmaf(p3, vv.y, o[3][1]);
            o[3][2] = fmaf(p3, vv.z, o[3][2]); o[3][3] = fmaf(p3, vv.w, o[3][3]);
        }
    }

    #pragma unroll
    for (int i = 0; i < 4; i++) {
        float inv = (lrow[i] > 0.f) ? (1.f / lrow[i]) : 0.f;
        int qg = q0 + 4 * ty + i;
        float4 v;
        v.x = o[i][0] * inv; v.y = o[i][1] * inv;
        v.z = o[i][2] * inv; v.w = o[i][3] * inv;
        *(float4*)(out + ((size_t)(b * Sc) + qg) * Dc + h * HDc + 4 * tx) = v;
    }
}

// ---------------------------------------------------------------------------
// Launcher
// ---------------------------------------------------------------------------
extern "C" void kernel_launch(void* const* d_in, const int* in_sizes, int n_in,
                              void* d_out, int out_size)
{
    const float*         inp   = (const float*)d_in[0];
    const unsigned char* mask  = (const unsigned char*)d_in[1];
    const int*           relm  = (const int*)d_in[2];
    const float*         qkv_w = (const float*)d_in[3];
    const float*         relA  = (const float*)d_in[4];
    const float*         o_w   = (const float*)d_in[5];
    const float*         w1    = (const float*)d_in[6];
    const float*         b1    = (const float*)d_in[7];
    const float*         w2    = (const float*)d_in[8];
    const float*         b2    = (const float*)d_in[9];
    const float*         ln1g  = (const float*)d_in[10];
    const float*         ln1b  = (const float*)d_in[11];
    const float*         ln2g  = (const float*)d_in[12];
    const float*         ln2b  = (const float*)d_in[13];
    float* out = (float*)d_out;

    float *p_xln, *p_qkv, *p_att, *p_res1, *p_hln, *p_ff;
    cudaGetSymbolAddress((void**)&p_xln,  g_xln);
    cudaGetSymbolAddress((void**)&p_qkv,  g_qkv);
    cudaGetSymbolAddress((void**)&p_att,  g_att);
    cudaGetSymbolAddress((void**)&p_res1, g_res1);
    cudaGetSymbolAddress((void**)&p_hln,  g_hln);
    cudaGetSymbolAddress((void**)&p_ff,   g_ff);

    cudaFuncSetAttribute(attn_kernel, cudaFuncAttributeMaxDynamicSharedMemorySize,
                         ATT_SMEM_FLOATS * (int)sizeof(float));

    // 1. LN1
    ln_kernel<<<Mrows, 256>>>(inp, ln1g, ln1b, p_xln);

    // 2. QKV = xln @ qkv_w^T       [2048 x 2304] k=768 -> BM=128, grid 18x16=288
    sgemm_db<128><<<dim3(3 * Dc / 128, Mrows / 128), 256>>>(
        p_xln, qkv_w, nullptr, nullptr, p_qkv, Mrows, 3 * Dc, Dc, 0);

    // 3. Fused attention
    attn_kernel<<<dim3(Sc / 64, Bc * Hc), 256, ATT_SMEM_FLOATS * sizeof(float)>>>(
        p_qkv, relm, mask, relA, p_att);

    // 4. res1 = inp + att @ o_w^T  [2048 x 768] -> BM=64, grid 6x32=192
    sgemm_db<64><<<dim3(Dc / 128, Mrows / 64), 256>>>(
        p_att, o_w, nullptr, inp, p_res1, Mrows, Dc, Dc, 0);

    // 5. LN2
    ln_kernel<<<Mrows, 256>>>(p_res1, ln2g, ln2b, p_hln);

    // 6. ff = relu(hln @ w1^T + b1)  [2048 x 3072] -> BM=128, grid 24x16=384
    sgemm_db<128><<<dim3(DFFc / 128, Mrows / 128), 256>>>(
        p_hln, w1, b1, nullptr, p_ff, Mrows, DFFc, Dc, 1);

    // 7. out = res1 + ff @ w2^T + b2  [2048 x 768] k=3072 -> BM=64, grid 6x32=192
    sgemm_db<64><<<dim3(Dc / 128, Mrows / 64), 256>>>(
        p_ff, w2, b2, p_res1, out, Mrows, Dc, DFFc, 0);
}

// round 9
// speedup vs baseline: 1.2162x; 1.0150x over previous
#include <cuda_runtime.h>
#include <math.h>

// Problem dimensions
#define Bc   2
#define Sc   1024
#define Dc   768
#define Hc   12
#define HDc  64
#define DFFc 3072
#define Mrows (Bc*Sc)          // 2048

// ---------------------------------------------------------------------------
// Scratch (allocation-free: __device__ globals)
// ---------------------------------------------------------------------------
__device__ float g_xln [Mrows*Dc];
__device__ float g_qkv [Mrows*3*Dc];
__device__ float g_att [Mrows*Dc];
__device__ float g_res1[Mrows*Dc];
__device__ float g_hln [Mrows*Dc];
__device__ float g_ff  [Mrows*DFFc];

// ---------------------------------------------------------------------------
// LayerNorm: one block per row of 768
// ---------------------------------------------------------------------------
__global__ __launch_bounds__(256) void ln_kernel(
    const float* __restrict__ x, const float* __restrict__ g,
    const float* __restrict__ b, float* __restrict__ y)
{
    __shared__ float red[16];
    int row = blockIdx.x;
    int t = threadIdx.x;
    const float* xr = x + (size_t)row * Dc;
    float v0 = xr[t], v1 = xr[t + 256], v2 = xr[t + 512];
    float s  = v0 + v1 + v2;
    float ss = v0*v0 + v1*v1 + v2*v2;
    #pragma unroll
    for (int o = 16; o > 0; o >>= 1) {
        s  += __shfl_xor_sync(0xffffffffu, s,  o);
        ss += __shfl_xor_sync(0xffffffffu, ss, o);
    }
    int w = t >> 5;
    if ((t & 31) == 0) { red[w] = s; red[8 + w] = ss; }
    __syncthreads();
    s = 0.f; ss = 0.f;
    #pragma unroll
    for (int i = 0; i < 8; i++) { s += red[i]; ss += red[8 + i]; }
    float mean = s * (1.0f / Dc);
    float var  = ss * (1.0f / Dc) - mean * mean;
    float inv  = rsqrtf(var + 1e-5f);
    float* yr = y + (size_t)row * Dc;
    yr[t]       = (v0 - mean) * inv * g[t]       + b[t];
    yr[t + 256] = (v1 - mean) * inv * g[t + 256] + b[t + 256];
    yr[t + 512] = (v2 - mean) * inv * g[t + 512] + b[t + 512];
}

// ---------------------------------------------------------------------------
// SGEMM (smem double-buffered + register-fragment double-buffered):
// C[M,N] = A[M,K]*B[N,K]^T (+bias)(relu)(+res)
// BN=128, BK=16, 256 threads. BM template: 128 (8x8/thread) or 64 (4x8).
// ---------------------------------------------------------------------------
template<int BM>
__global__ __launch_bounds__(256, 2) void sgemm_db(
    const float* __restrict__ A, const float* __restrict__ B,
    const float* __restrict__ bias, const float* __restrict__ res,
    float* __restrict__ C, int M, int N, int K, int do_relu)
{
    constexpr int BN = 128;
    constexpr int BK = 16;
    constexpr int TM = BM / 16;          // 8 or 4
    constexpr int AV = BM / 64;          // float4s per thread for A tile (2 or 1)

    __shared__ float As[2][BK][BM];
    __shared__ float Bs[2][BK][BN];

    int tid = threadIdx.x;
    int tx = tid & 15, ty = tid >> 4;
    int bm = blockIdx.y * BM, bn = blockIdx.x * BN;

    int arow, akq;
    if (BM == 128) { arow = tid >> 1; akq = (tid & 1) * 8; }
    else           { arow = tid >> 2; akq = (tid & 3) * 4; }
    int brow = tid >> 1, bkq = (tid & 1) * 8;

    const float* Ag = A + (size_t)(bm + arow) * K + akq;
    const float* Bg = B + (size_t)(bn + brow) * K + bkq;

    float4 areg[AV], breg[2];

    float acc[TM][8];
    #pragma unroll
    for (int i = 0; i < TM; i++)
        #pragma unroll
        for (int j = 0; j < 8; j++) acc[i][j] = 0.f;

    // prologue: load tile 0 into regs, store to buffer 0
    #pragma unroll
    for (int v = 0; v < AV; v++) areg[v] = *(const float4*)(Ag + 4 * v);
    breg[0] = *(const float4*)(Bg);
    breg[1] = *(const float4*)(Bg + 4);

    #pragma unroll
    for (int v = 0; v < AV; v++) {
        As[0][akq + 4*v + 0][arow] = areg[v].x;
        As[0][akq + 4*v + 1][arow] = areg[v].y;
        As[0][akq + 4*v + 2][arow] = areg[v].z;
        As[0][akq + 4*v + 3][arow] = areg[v].w;
    }
    #pragma unroll
    for (int v = 0; v < 2; v++) {
        Bs[0][bkq + 4*v + 0][brow] = breg[v].x;
        Bs[0][bkq + 4*v + 1][brow] = breg[v].y;
        Bs[0][bkq + 4*v + 2][brow] = breg[v].z;
        Bs[0][bkq + 4*v + 3][brow] = breg[v].w;
    }
    __syncthreads();

    float af[2][TM], bf[2][8];

    int nt = K / BK;
    for (int kt = 0; kt < nt; kt++) {
        int cur = kt & 1;
        // global prefetch of next tile
        if (kt + 1 < nt) {
            const float* Ag2 = Ag + (size_t)(kt + 1) * BK;
            const float* Bg2 = Bg + (size_t)(kt + 1) * BK;
            #pragma unroll
            for (int v = 0; v < AV; v++) areg[v] = *(const float4*)(Ag2 + 4 * v);
            breg[0] = *(const float4*)(Bg2);
            breg[1] = *(const float4*)(Bg2 + 4);
        }

        // preload fragments for kk=0
        {
            if (BM == 128) {
                float4 a0 = *(const float4*)&As[cur][0][4 * ty];
                float4 a1 = *(const float4*)&As[cur][0][64 + 4 * ty];
                af[0][0] = a0.x; af[0][1] = a0.y; af[0][2] = a0.z; af[0][3] = a0.w;
                af[0][4] = a1.x; af[0][5] = a1.y; af[0][6] = a1.z; af[0][7] = a1.w;
            } else {
                float4 a0 = *(const float4*)&As[cur][0][4 * ty];
                af[0][0] = a0.x; af[0][1] = a0.y; af[0][2] = a0.z; af[0][3] = a0.w;
            }
            float4 b0 = *(const float4*)&Bs[cur][0][4 * tx];
            float4 b1 = *(const float4*)&Bs[cur][0][64 + 4 * tx];
            bf[0][0] = b0.x; bf[0][1] = b0.y; bf[0][2] = b0.z; bf[0][3] = b0.w;
            bf[0][4] = b1.x; bf[0][5] = b1.y; bf[0][6] = b1.z; bf[0][7] = b1.w;
        }

        #pragma unroll
        for (int kk = 0; kk < BK; kk++) {
            int c = kk & 1, n = c ^ 1;
            if (kk + 1 < BK) {
                if (BM == 128) {
                    float4 a0 = *(const float4*)&As[cur][kk + 1][4 * ty];
                    float4 a1 = *(const float4*)&As[cur][kk + 1][64 + 4 * ty];
                    af[n][0] = a0.x; af[n][1] = a0.y; af[n][2] = a0.z; af[n][3] = a0.w;
                    af[n][4] = a1.x; af[n][5] = a1.y; af[n][6] = a1.z; af[n][7] = a1.w;
                } else {
                    float4 a0 = *(const float4*)&As[cur][kk + 1][4 * ty];
                    af[n][0] = a0.x; af[n][1] = a0.y; af[n][2] = a0.z; af[n][3] = a0.w;
                }
                float4 b0 = *(const float4*)&Bs[cur][kk + 1][4 * tx];
                float4 b1 = *(const float4*)&Bs[cur][kk + 1][64 + 4 * tx];
                bf[n][0] = b0.x; bf[n][1] = b0.y; bf[n][2] = b0.z; bf[n][3] = b0.w;
                bf[n][4] = b1.x; bf[n][5] = b1.y; bf[n][6] = b1.z; bf[n][7] = b1.w;
            }
            #pragma unroll
            for (int i = 0; i < TM; i++)
                #pragma unroll
                for (int j = 0; j < 8; j++)
                    acc[i][j] = fmaf(af[c][i], bf[c][j], acc[i][j]);
        }

        if (kt + 1 < nt) {
            int nxt = cur ^ 1;
            #pragma unroll
            for (int v = 0; v < AV; v++) {
                As[nxt][akq + 4*v + 0][arow] = areg[v].x;
                As[nxt][akq + 4*v + 1][arow] = areg[v].y;
                As[nxt][akq + 4*v + 2][arow] = areg[v].z;
                As[nxt][akq + 4*v + 3][arow] = areg[v].w;
            }
            #pragma unroll
            for (int v = 0; v < 2; v++) {
                Bs[nxt][bkq + 4*v + 0][brow] = breg[v].x;
                Bs[nxt][bkq + 4*v + 1][brow] = breg[v].y;
                Bs[nxt][bkq + 4*v + 2][brow] = breg[v].z;
                Bs[nxt][bkq + 4*v + 3][brow] = breg[v].w;
            }
            __syncthreads();
        }
    }

    // Epilogue
    #pragma unroll
    for (int i = 0; i < TM; i++) {
        int r;
        if (BM == 128) r = bm + ((i < 4) ? (4 * ty + i) : (64 + 4 * ty + (i - 4)));
        else           r = bm + 4 * ty + i;
        #pragma unroll
        for (int half = 0; half < 2; half++) {
            int c0 = bn + half * 64 + 4 * tx;
            float4 v;
            v.x = acc[i][half * 4 + 0];
            v.y = acc[i][half * 4 + 1];
            v.z = acc[i][half * 4 + 2];
            v.w = acc[i][half * 4 + 3];
            if (bias) {
                v.x += bias[c0 + 0]; v.y += bias[c0 + 1];
                v.z += bias[c0 + 2]; v.w += bias[c0 + 3];
            }
            if (do_relu) {
                v.x = fmaxf(v.x, 0.f); v.y = fmaxf(v.y, 0.f);
                v.z = fmaxf(v.z, 0.f); v.w = fmaxf(v.w, 0.f);
            }
            if (res) {
                float4 rv = *(const float4*)(res + (size_t)r * N + c0);
                v.x += rv.x; v.y += rv.y; v.z += rv.z; v.w += rv.w;
            }
            *(float4*)(C + (size_t)r * N + c0) = v;
        }
    }
}

// ---------------------------------------------------------------------------
// Fused attention (flash-style): per (q-block of 64, b*h)
// ---------------------------------------------------------------------------
#define ATT_SMEM_FLOATS (64*64 + 64*65 + 64*64 + 64*4)

__global__ __launch_bounds__(256) void attn_kernel(
    const float* __restrict__ qkv,          // [B,S,3D]
    const int* __restrict__ relm,           // [B,S,S]
    const unsigned char* __restrict__ mask, // [B,S] (bool)
    const float* __restrict__ relA,         // [3,64]
    float* __restrict__ out)                // [B,S,D]
{
    extern __shared__ float sm[];
    float* QS = sm;                 // 64*64
    float* KP = QS + 64 * 64;       // 64*65 (padded stride 65)
    float* VS = KP + 64 * 65;       // 64*64
    float* RR = VS + 64 * 64;       // 64*4

    int tid = threadIdx.x;
    int tx = tid & 15, ty = tid >> 4;
    int qb = blockIdx.x;            // 0..15
    int bh = blockIdx.y;            // 0..23
    int b = bh / Hc, h = bh % Hc;
    int q0 = qb * 64;

    const float* qbase = qkv + (size_t)(b * Sc) * (3 * Dc) + h * HDc;
    const float* kbase = qbase + Dc;
    const float* vbase = qbase + 2 * Dc;

    {
        int col4 = (tid & 15) * 4;
        for (int r = tid >> 4; r < 64; r += 16) {
            float4 v = *(const float4*)(qbase + (size_t)(q0 + r) * (3 * Dc) + col4);
            *(float4*)&QS[r * 64 + col4] = v;
        }
    }
    __syncthreads();

    if (tid < 192) {
        int q = tid / 3, c = tid % 3;
        float s = 0.f;
        const float* arow = relA + c * HDc;
        #pragma unroll 8
        for (int d = 0; d < 64; d++) s += QS[q * 64 + d] * arow[d];
        RR[q * 4 + c] = s;
    }
    __syncthreads();

    float mrow[4], lrow[4], o[4][4];
    #pragma unroll
    for (int i = 0; i < 4; i++) {
        mrow[i] = -INFINITY; lrow[i] = 0.f;
        #pragma unroll
        for (int j = 0; j < 4; j++) o[i][j] = 0.f;
    }

    const int* rmrow = relm + ((size_t)b * Sc + q0) * Sc;
    const unsigned char* mkrow = mask + (size_t)b * Sc;

    for (int kb = 0; kb < Sc / 64; kb++) {
        int k0 = kb * 64;
        __syncthreads();
        {
            int col4 = (tid & 15) * 4;
            for (int r = tid >> 4; r < 64; r += 16) {
                float4 kv = *(const float4*)(kbase + (size_t)(k0 + r) * (3 * Dc) + col4);
                KP[r * 65 + col4 + 0] = kv.x; KP[r * 65 + col4 + 1] = kv.y;
                KP[r * 65 + col4 + 2] = kv.z; KP[r * 65 + col4 + 3] = kv.w;
                float4 vv = *(const float4*)(vbase + (size_t)(k0 + r) * (3 * Dc) + col4);
                *(float4*)&VS[r * 64 + col4] = vv;
            }
        }
        __syncthreads();

        float s[4][4];
        #pragma unroll
        for (int i = 0; i < 4; i++)
            #pragma unroll
            for (int j = 0; j < 4; j++) s[i][j] = 0.f;
        #pragma unroll 4
        for (int d = 0; d < 64; d++) {
            float a0 = QS[(4 * ty + 0) * 64 + d];
            float a1 = QS[(4 * ty + 1) * 64 + d];
            float a2 = QS[(4 * ty + 2) * 64 + d];
            float a3 = QS[(4 * ty + 3) * 64 + d];
            float b0 = KP[(4 * tx + 0) * 65 + d];
            float b1 = KP[(4 * tx + 1) * 65 + d];
            float b2 = KP[(4 * tx + 2) * 65 + d];
            float b3 = KP[(4 * tx + 3) * 65 + d];
            s[0][0] = fmaf(a0, b0, s[0][0]); s[0][1] = fmaf(a0, b1, s[0][1]);
            s[0][2] = fmaf(a0, b2, s[0][2]); s[0][3] = fmaf(a0, b3, s[0][3]);
            s[1][0] = fmaf(a1, b0, s[1][0]); s[1][1] = fmaf(a1, b1, s[1][1]);
            s[1][2] = fmaf(a1, b2, s[1][2]); s[1][3] = fmaf(a1, b3, s[1][3]);
            s[2][0] = fmaf(a2, b0, s[2][0]); s[2][1] = fmaf(a2, b1, s[2][1]);
            s[2][2] = fmaf(a2, b2, s[2][2]); s[2][3] = fmaf(a2, b3, s[2][3]);
            s[3][0] = fmaf(a3, b0, s[3][0]); s[3][1] = fmaf(a3, b1, s[3][1]);
            s[3][2] = fmaf(a3, b2, s[3][2]); s[3][3] = fmaf(a3, b3, s[3][3]);
        }

        #pragma unroll
        for (int j = 0; j < 4; j++) {
            int kg = k0 + 4 * tx + j;
            unsigned char mk = mkrow[kg];
            #pragma unroll
            for (int i = 0; i < 4; i++) {
                int ql = 4 * ty + i;
                int idx = rmrow[(size_t)ql * Sc + kg] + 1;   // 0,1,2
                float val = (s[i][j] + RR[ql * 4 + idx]) * 0.125f;
                s[i][j] = mk ? -INFINITY : val;
            }
        }

        #pragma unroll
        for (int i = 0; i < 4; i++) {
            float tm = fmaxf(fmaxf(s[i][0], s[i][1]), fmaxf(s[i][2], s[i][3]));
            #pragma unroll
            for (int off = 1; off < 16; off <<= 1)
                tm = fmaxf(tm, __shfl_xor_sync(0xffffffffu, tm, off));
            float nm = fmaxf(mrow[i], tm);
            if (nm == -INFINITY) continue;
            float alpha = (mrow[i] == -INFINITY) ? 0.f : __expf(mrow[i] - nm);
            float rs = 0.f;
            #pragma unroll
            for (int j = 0; j < 4; j++) {
                s[i][j] = __expf(s[i][j] - nm);
                rs += s[i][j];
            }
            #pragma unroll
            for (int off = 1; off < 16; off <<= 1)
                rs += __shfl_xor_sync(0xffffffffu, rs, off);
            lrow[i] = lrow[i] * alpha + rs;
            #pragma unroll
            for (int j = 0; j < 4; j++) o[i][j] *= alpha;
            mrow[i] = nm;
        }

        __syncthreads();
        #pragma unroll
        for (int i = 0; i < 4; i++)
            #pragma unroll
            for (int j = 0; j < 4; j++)
                KP[(4 * ty + i) * 65 + 4 * tx + j] = (mrow[i] == -INFINITY) ? 0.f : s[i][j];
        __syncthreads();

        #pragma unroll 4
        for (int k = 0; k < 64; k++) {
            float4 vv = *(const float4*)&VS[k * 64 + 4 * tx];
            float p0 = KP[(4 * ty + 0) * 65 + k];
            float p1 = KP[(4 * ty + 1) * 65 + k];
            float p2 = KP[(4 * ty + 2) * 65 + k];
            float p3 = KP[(4 * ty + 3) * 65 + k];
            o[0][0] = fmaf(p0, vv.x, o[0][0]); o[0][1] = fmaf(p0, vv.y, o[0][1]);
            o[0][2] = fmaf(p0, vv.z, o[0][2]); o[0][3] = fmaf(p0, vv.w, o[0][3]);
            o[1][0] = fmaf(p1, vv.x, o[1][0]); o[1][1] = fmaf(p1, vv.y, o[1][1]);
            o[1][2] = fmaf(p1, vv.z, o[1][2]); o[1][3] = fmaf(p1, vv.w, o[1][3]);
            o[2][0] = fmaf(p2, vv.x, o[2][0]); o[2][1] = fmaf(p2, vv.y, o[2][1]);
            o[2][2] = fmaf(p2, vv.z, o[2][2]); o[2][3] = fmaf(p2, vv.w, o[2][3]);
            o[3][0] = fmaf(p3, vv.x, o[3][0]); o[3][1] = fmaf(p3, vv.y, o[3][1]);
            o[3][2] = fmaf(p3, vv.z, o[3][2]); o[3][3] = fmaf(p3, vv.w, o[3][3]);
        }
    }

    #pragma unroll
    for (int i = 0; i < 4; i++) {
        float inv = (lrow[i] > 0.f) ? (1.f / lrow[i]) : 0.f;
        int qg = q0 + 4 * ty + i;
        float4 v;
        v.x = o[i][0] * inv; v.y = o[i][1] * inv;
        v.z = o[i][2] * inv; v.w = o[i][3] * inv;
        *(float4*)(out + ((size_t)(b * Sc) + qg) * Dc + h * HDc + 4 * tx) = v;
    }
}

// ---------------------------------------------------------------------------
// Launcher
// ---------------------------------------------------------------------------
extern "C" void kernel_launch(void* const* d_in, const int* in_sizes, int n_in,
                              void* d_out, int out_size)
{
    const float*         inp   = (const float*)d_in[0];
    const unsigned char* mask  = (const unsigned char*)d_in[1];
    const int*           relm  = (const int*)d_in[2];
    const float*         qkv_w = (const float*)d_in[3];
    const float*         relA  = (const float*)d_in[4];
    const float*         o_w   = (const float*)d_in[5];
    const float*         w1    = (const float*)d_in[6];
    const float*         b1    = (const float*)d_in[7];
    const float*         w2    = (const float*)d_in[8];
    const float*         b2    = (const float*)d_in[9];
    const float*         ln1g  = (const float*)d_in[10];
    const float*         ln1b  = (const float*)d_in[11];
    const float*         ln2g  = (const float*)d_in[12];
    const float*         ln2b  = (const float*)d_in[13];
    float* out = (float*)d_out;

    float *p_xln, *p_qkv, *p_att, *p_res1, *p_hln, *p_ff;
    cudaGetSymbolAddress((void**)&p_xln,  g_xln);
    cudaGetSymbolAddress((void**)&p_qkv,  g_qkv);
    cudaGetSymbolAddress((void**)&p_att,  g_att);
    cudaGetSymbolAddress((void**)&p_res1, g_res1);
    cudaGetSymbolAddress((void**)&p_hln,  g_hln);
    cudaGetSymbolAddress((void**)&p_ff,   g_ff);

    cudaFuncSetAttribute(attn_kernel, cudaFuncAttributeMaxDynamicSharedMemorySize,
                         ATT_SMEM_FLOATS * (int)sizeof(float));

    // 1. LN1
    ln_kernel<<<Mrows, 256>>>(inp, ln1g, ln1b, p_xln);

    // 2. QKV = xln @ qkv_w^T       [2048 x 2304] k=768 -> BM=128, grid 18x16=288
    sgemm_db<128><<<dim3(3 * Dc / 128, Mrows / 128), 256>>>(
        p_xln, qkv_w, nullptr, nullptr, p_qkv, Mrows, 3 * Dc, Dc, 0);

    // 3. Fused attention
    attn_kernel<<<dim3(Sc / 64, Bc * Hc), 256, ATT_SMEM_FLOATS * sizeof(float)>>>(
        p_qkv, relm, mask, relA, p_att);

    // 4. res1 = inp + att @ o_w^T  [2048 x 768] -> BM=64, grid 6x32=192
    sgemm_db<64><<<dim3(Dc / 128, Mrows / 64), 256>>>(
        p_att, o_w, nullptr, inp, p_res1, Mrows, Dc, Dc, 0);

    // 5. LN2
    ln_kernel<<<Mrows, 256>>>(p_res1, ln2g, ln2b, p_hln);

    // 6. ff = relu(hln @ w1^T + b1)  [2048 x 3072] -> BM=128, grid 24x16=384
    sgemm_db<128><<<dim3(DFFc / 128, Mrows / 128), 256>>>(
        p_hln, w1, b1, nullptr, p_ff, Mrows, DFFc, Dc, 1);

    // 7. out = res1 + ff @ w2^T + b2  [2048 x 768] k=3072 -> BM=64, grid 6x32=192
    sgemm_db<64><<<dim3(Dc / 128, Mrows / 64), 256>>>(
        p_ff, w2, b2, p_res1, out, Mrows, Dc, DFFc, 0);
}

// round 10
// speedup vs baseline: 1.2400x; 1.0196x over previous
#include <cuda_runtime.h>
#include <math.h>

// Problem dimensions
#define Bc   2
#define Sc   1024
#define Dc   768
#define Hc   12
#define HDc  64
#define DFFc 3072
#define Mrows (Bc*Sc)          // 2048

// Packed f32x2 helpers (FFMA2 path — PTX-only)
#define FMA_F32X2(d, a, b, c) \
    asm("fma.rn.f32x2 %0, %1, %2, %3;" : "=l"(d) : "l"(a), "l"(b), "l"(c))
#define PACK2F(out, lo, hi) \
    asm("mov.b64 %0, {%1, %2};" : "=l"(out) : "f"(lo), "f"(hi))
#define UNPACK2F(lo, hi, in) \
    asm("mov.b64 {%0, %1}, %2;" : "=f"(lo), "=f"(hi) : "l"(in))

// ---------------------------------------------------------------------------
// Scratch (allocation-free: __device__ globals)
// ---------------------------------------------------------------------------
__device__ float g_xln [Mrows*Dc];
__device__ float g_qkv [Mrows*3*Dc];
__device__ float g_att [Mrows*Dc];
__device__ float g_res1[Mrows*Dc];
__device__ float g_hln [Mrows*Dc];
__device__ float g_ff  [Mrows*DFFc];

// ---------------------------------------------------------------------------
// LayerNorm: one block per row of 768
// ---------------------------------------------------------------------------
__global__ __launch_bounds__(256) void ln_kernel(
    const float* __restrict__ x, const float* __restrict__ g,
    const float* __restrict__ b, float* __restrict__ y)
{
    __shared__ float red[16];
    int row = blockIdx.x;
    int t = threadIdx.x;
    const float* xr = x + (size_t)row * Dc;
    float v0 = xr[t], v1 = xr[t + 256], v2 = xr[t + 512];
    float s  = v0 + v1 + v2;
    float ss = v0*v0 + v1*v1 + v2*v2;
    #pragma unroll
    for (int o = 16; o > 0; o >>= 1) {
        s  += __shfl_xor_sync(0xffffffffu, s,  o);
        ss += __shfl_xor_sync(0xffffffffu, ss, o);
    }
    int w = t >> 5;
    if ((t & 31) == 0) { red[w] = s; red[8 + w] = ss; }
    __syncthreads();
    s = 0.f; ss = 0.f;
    #pragma unroll
    for (int i = 0; i < 8; i++) { s += red[i]; ss += red[8 + i]; }
    float mean = s * (1.0f / Dc);
    float var  = ss * (1.0f / Dc) - mean * mean;
    float inv  = rsqrtf(var + 1e-5f);
    float* yr = y + (size_t)row * Dc;
    yr[t]       = (v0 - mean) * inv * g[t]       + b[t];
    yr[t + 256] = (v1 - mean) * inv * g[t + 256] + b[t + 256];
    yr[t + 512] = (v2 - mean) * inv * g[t + 512] + b[t + 512];
}

// ---------------------------------------------------------------------------
// SGEMM, packed-f32x2 inner product (FFMA2):
// C[M,N] = A[M,K]*B[N,K]^T (+bias)(relu)(+res)
// Tile 64x128, BK=16, 128 threads, 8x8 per thread. Smem double-buffered.
// ---------------------------------------------------------------------------
__global__ __launch_bounds__(128, 4) void sgemm_x2(
    const float* __restrict__ A, const float* __restrict__ B,
    const float* __restrict__ bias, const float* __restrict__ res,
    float* __restrict__ C, int M, int N, int K, int do_relu)
{
    constexpr int BM = 64, BN = 128, BK = 16;

    __shared__ float As[2][BK][BM];    // 4 KB per buffer
    __shared__ float Bs[2][BK][BN];    // 8 KB per buffer

    int tid = threadIdx.x;
    int tx = tid & 15;          // 0..15 -> column groups
    int ty = tid >> 4;          // 0..7  -> row groups (8 rows each)
    int bm = blockIdx.y * BM, bn = blockIdx.x * BN;

    // global->smem load mapping
    int arow = tid >> 1;             // 0..63
    int akq  = (tid & 1) * 8;        // 0 or 8 (loads 8 consecutive k)
    const float* Ag = A + (size_t)(bm + arow) * K + akq;
    const float* Bg = B + (size_t)(bn + tid) * K;    // each thread one B row, 16 k

    float4 areg[2], breg[4];

    unsigned long long acc[8][4];
    #pragma unroll
    for (int i = 0; i < 8; i++)
        #pragma unroll
        for (int j = 0; j < 4; j++) acc[i][j] = 0ull;

    // prologue: tile 0
    areg[0] = *(const float4*)(Ag);
    areg[1] = *(const float4*)(Ag + 4);
    #pragma unroll
    for (int v = 0; v < 4; v++) breg[v] = *(const float4*)(Bg + 4 * v);

    #pragma unroll
    for (int v = 0; v < 2; v++) {
        As[0][akq + 4*v + 0][arow] = (&areg[v].x)[0];
        As[0][akq + 4*v + 1][arow] = (&areg[v].x)[1];
        As[0][akq + 4*v + 2][arow] = (&areg[v].x)[2];
        As[0][akq + 4*v + 3][arow] = (&areg[v].x)[3];
    }
    #pragma unroll
    for (int v = 0; v < 4; v++) {
        Bs[0][4*v + 0][tid] = breg[v].x;
        Bs[0][4*v + 1][tid] = breg[v].y;
        Bs[0][4*v + 2][tid] = breg[v].z;
        Bs[0][4*v + 3][tid] = breg[v].w;
    }
    __syncthreads();

    int nt = K / BK;
    for (int kt = 0; kt < nt; kt++) {
        int cur = kt & 1;
        if (kt + 1 < nt) {
            const float* Ag2 = Ag + (size_t)(kt + 1) * BK;
            const float* Bg2 = Bg + (size_t)(kt + 1) * BK;
            areg[0] = *(const float4*)(Ag2);
            areg[1] = *(const float4*)(Ag2 + 4);
            #pragma unroll
            for (int v = 0; v < 4; v++) breg[v] = *(const float4*)(Bg2 + 4 * v);
        }

        #pragma unroll
        for (int kk = 0; kk < BK; kk++) {
            float4 a0 = *(const float4*)&As[cur][kk][8 * ty];
            float4 a1 = *(const float4*)&As[cur][kk][8 * ty + 4];
            float4 b0 = *(const float4*)&Bs[cur][kk][4 * tx];
            float4 b1 = *(const float4*)&Bs[cur][kk][64 + 4 * tx];

            unsigned long long ap[8], bp[4];
            PACK2F(ap[0], a0.x, a0.x); PACK2F(ap[1], a0.y, a0.y);
            PACK2F(ap[2], a0.z, a0.z); PACK2F(ap[3], a0.w, a0.w);
            PACK2F(ap[4], a1.x, a1.x); PACK2F(ap[5], a1.y, a1.y);
            PACK2F(ap[6], a1.z, a1.z); PACK2F(ap[7], a1.w, a1.w);
            PACK2F(bp[0], b0.x, b0.y); PACK2F(bp[1], b0.z, b0.w);
            PACK2F(bp[2], b1.x, b1.y); PACK2F(bp[3], b1.z, b1.w);

            #pragma unroll
            for (int i = 0; i < 8; i++)
                #pragma unroll
                for (int j = 0; j < 4; j++)
                    FMA_F32X2(acc[i][j], ap[i], bp[j], acc[i][j]);
        }

        if (kt + 1 < nt) {
            int nxt = cur ^ 1;
            #pragma unroll
            for (int v = 0; v < 2; v++) {
                As[nxt][akq + 4*v + 0][arow] = (&areg[v].x)[0];
                As[nxt][akq + 4*v + 1][arow] = (&areg[v].x)[1];
                As[nxt][akq + 4*v + 2][arow] = (&areg[v].x)[2];
                As[nxt][akq + 4*v + 3][arow] = (&areg[v].x)[3];
            }
            #pragma unroll
            for (int v = 0; v < 4; v++) {
                Bs[nxt][4*v + 0][tid] = breg[v].x;
                Bs[nxt][4*v + 1][tid] = breg[v].y;
                Bs[nxt][4*v + 2][tid] = breg[v].z;
                Bs[nxt][4*v + 3][tid] = breg[v].w;
            }
            __syncthreads();
        }
    }

    // Epilogue: unpack pairs, fuse bias/relu/residual, store float4s
    #pragma unroll
    for (int i = 0; i < 8; i++) {
        int r = bm + 8 * ty + i;
        float o[8];
        UNPACK2F(o[0], o[1], acc[i][0]);
        UNPACK2F(o[2], o[3], acc[i][1]);
        UNPACK2F(o[4], o[5], acc[i][2]);
        UNPACK2F(o[6], o[7], acc[i][3]);
        #pragma unroll
        for (int half = 0; half < 2; half++) {
            int c0 = bn + half * 64 + 4 * tx;
            float4 v;
            v.x = o[half * 4 + 0]; v.y = o[half * 4 + 1];
            v.z = o[half * 4 + 2]; v.w = o[half * 4 + 3];
            if (bias) {
                v.x += bias[c0 + 0]; v.y += bias[c0 + 1];
                v.z += bias[c0 + 2]; v.w += bias[c0 + 3];
            }
            if (do_relu) {
                v.x = fmaxf(v.x, 0.f); v.y = fmaxf(v.y, 0.f);
                v.z = fmaxf(v.z, 0.f); v.w = fmaxf(v.w, 0.f);
            }
            if (res) {
                float4 rv = *(const float4*)(res + (size_t)r * N + c0);
                v.x += rv.x; v.y += rv.y; v.z += rv.z; v.w += rv.w;
            }
            *(float4*)(C + (size_t)r * N + c0) = v;
        }
    }
}

// ---------------------------------------------------------------------------
// Fused attention (flash-style): per (q-block of 64, b*h)
// ---------------------------------------------------------------------------
#define ATT_SMEM_FLOATS (64*64 + 64*65 + 64*64 + 64*4)

__global__ __launch_bounds__(256) void attn_kernel(
    const float* __restrict__ qkv,          // [B,S,3D]
    const int* __restrict__ relm,           // [B,S,S]
    const unsigned char* __restrict__ mask, // [B,S] (bool)
    const float* __restrict__ relA,         // [3,64]
    float* __restrict__ out)                // [B,S,D]
{
    extern __shared__ float sm[];
    float* QS = sm;                 // 64*64
    float* KP = QS + 64 * 64;       // 64*65 (padded stride 65)
    float* VS = KP + 64 * 65;       // 64*64
    float* RR = VS + 64 * 64;       // 64*4

    int tid = threadIdx.x;
    int tx = tid & 15, ty = tid >> 4;
    int qb = blockIdx.x;            // 0..15
    int bh = blockIdx.y;            // 0..23
    int b = bh / Hc, h = bh % Hc;
    int q0 = qb * 64;

    const float* qbase = qkv + (size_t)(b * Sc) * (3 * Dc) + h * HDc;
    const float* kbase = qbase + Dc;
    const float* vbase = qbase + 2 * Dc;

    {
        int col4 = (tid & 15) * 4;
        for (int r = tid >> 4; r < 64; r += 16) {
            float4 v = *(const float4*)(qbase + (size_t)(q0 + r) * (3 * Dc) + col4);
            *(float4*)&QS[r * 64 + col4] = v;
        }
    }
    __syncthreads();

    if (tid < 192) {
        int q = tid / 3, c = tid % 3;
        float s = 0.f;
        const float* arow = relA + c * HDc;
        #pragma unroll 8
        for (int d = 0; d < 64; d++) s += QS[q * 64 + d] * arow[d];
        RR[q * 4 + c] = s;
    }
    __syncthreads();

    float mrow[4], lrow[4], o[4][4];
    #pragma unroll
    for (int i = 0; i < 4; i++) {
        mrow[i] = -INFINITY; lrow[i] = 0.f;
        #pragma unroll
        for (int j = 0; j < 4; j++) o[i][j] = 0.f;
    }

    const int* rmrow = relm + ((size_t)b * Sc + q0) * Sc;
    const unsigned char* mkrow = mask + (size_t)b * Sc;

    for (int kb = 0; kb < Sc / 64; kb++) {
        int k0 = kb * 64;
        __syncthreads();
        {
            int col4 = (tid & 15) * 4;
            for (int r = tid >> 4; r < 64; r += 16) {
                float4 kv = *(const float4*)(kbase + (size_t)(k0 + r) * (3 * Dc) + col4);
                KP[r * 65 + col4 + 0] = kv.x; KP[r * 65 + col4 + 1] = kv.y;
                KP[r * 65 + col4 + 2] = kv.z; KP[r * 65 + col4 + 3] = kv.w;
                float4 vv = *(const float4*)(vbase + (size_t)(k0 + r) * (3 * Dc) + col4);
                *(float4*)&VS[r * 64 + col4] = vv;
            }
        }
        __syncthreads();

        float s[4][4];
        #pragma unroll
        for (int i = 0; i < 4; i++)
            #pragma unroll
            for (int j = 0; j < 4; j++) s[i][j] = 0.f;
        #pragma unroll 4
        for (int d = 0; d < 64; d++) {
            float a0 = QS[(4 * ty + 0) * 64 + d];
            float a1 = QS[(4 * ty + 1) * 64 + d];
            float a2 = QS[(4 * ty + 2) * 64 + d];
            float a3 = QS[(4 * ty + 3) * 64 + d];
            float b0 = KP[(4 * tx + 0) * 65 + d];
            float b1 = KP[(4 * tx + 1) * 65 + d];
            float b2 = KP[(4 * tx + 2) * 65 + d];
            float b3 = KP[(4 * tx + 3) * 65 + d];
            s[0][0] = fmaf(a0, b0, s[0][0]); s[0][1] = fmaf(a0, b1, s[0][1]);
            s[0][2] = fmaf(a0, b2, s[0][2]); s[0][3] = fmaf(a0, b3, s[0][3]);
            s[1][0] = fmaf(a1, b0, s[1][0]); s[1][1] = fmaf(a1, b1, s[1][1]);
            s[1][2] = fmaf(a1, b2, s[1][2]); s[1][3] = fmaf(a1, b3, s[1][3]);
            s[2][0] = fmaf(a2, b0, s[2][0]); s[2][1] = fmaf(a2, b1, s[2][1]);
            s[2][2] = fmaf(a2, b2, s[2][2]); s[2][3] = fmaf(a2, b3, s[2][3]);
            s[3][0] = fmaf(a3, b0, s[3][0]); s[3][1] = fmaf(a3, b1, s[3][1]);
            s[3][2] = fmaf(a3, b2, s[3][2]); s[3][3] = fmaf(a3, b3, s[3][3]);
        }

        #pragma unroll
        for (int j = 0; j < 4; j++) {
            int kg = k0 + 4 * tx + j;
            unsigned char mk = mkrow[kg];
            #pragma unroll
            for (int i = 0; i < 4; i++) {
                int ql = 4 * ty + i;
                int idx = rmrow[(size_t)ql * Sc + kg] + 1;   // 0,1,2
                float val = (s[i][j] + RR[ql * 4 + idx]) * 0.125f;
                s[i][j] = mk ? -INFINITY : val;
            }
        }

        #pragma unroll
        for (int i = 0; i < 4; i++) {
            float tm = fmaxf(fmaxf(s[i][0], s[i][1]), fmaxf(s[i][2], s[i][3]));
            #pragma unroll
            for (int off = 1; off < 16; off <<= 1)
                tm = fmaxf(tm, __shfl_xor_sync(0xffffffffu, tm, off));
            float nm = fmaxf(mrow[i], tm);
            if (nm == -INFINITY) continue;
            float alpha = (mrow[i] == -INFINITY) ? 0.f : __expf(mrow[i] - nm);
            float rs = 0.f;
            #pragma unroll
            for (int j = 0; j < 4; j++) {
                s[i][j] = __expf(s[i][j] - nm);
                rs += s[i][j];
            }
            #pragma unroll
            for (int off = 1; off < 16; off <<= 1)
                rs += __shfl_xor_sync(0xffffffffu, rs, off);
            lrow[i] = lrow[i] * alpha + rs;
            #pragma unroll
            for (int j = 0; j < 4; j++) o[i][j] *= alpha;
            mrow[i] = nm;
        }

        __syncthreads();
        #pragma unroll
        for (int i = 0; i < 4; i++)
            #pragma unroll
            for (int j = 0; j < 4; j++)
                KP[(4 * ty + i) * 65 + 4 * tx + j] = (mrow[i] == -INFINITY) ? 0.f : s[i][j];
        __syncthreads();

        #pragma unroll 4
        for (int k = 0; k < 64; k++) {
            float4 vv = *(const float4*)&VS[k * 64 + 4 * tx];
            float p0 = KP[(4 * ty + 0) * 65 + k];
            float p1 = KP[(4 * ty + 1) * 65 + k];
            float p2 = KP[(4 * ty + 2) * 65 + k];
            float p3 = KP[(4 * ty + 3) * 65 + k];
            o[0][0] = fmaf(p0, vv.x, o[0][0]); o[0][1] = fmaf(p0, vv.y, o[0][1]);
            o[0][2] = fmaf(p0, vv.z, o[0][2]); o[0][3] = fmaf(p0, vv.w, o[0][3]);
            o[1][0] = fmaf(p1, vv.x, o[1][0]); o[1][1] = fmaf(p1, vv.y, o[1][1]);
            o[1][2] = fmaf(p1, vv.z, o[1][2]); o[1][3] = fmaf(p1, vv.w, o[1][3]);
            o[2][0] = fmaf(p2, vv.x, o[2][0]); o[2][1] = fmaf(p2, vv.y, o[2][1]);
            o[2][2] = fmaf(p2, vv.z, o[2][2]); o[2][3] = fmaf(p2, vv.w, o[2][3]);
            o[3][0] = fmaf(p3, vv.x, o[3][0]); o[3][1] = fmaf(p3, vv.y, o[3][1]);
            o[3][2] = fmaf(p3, vv.z, o[3][2]); o[3][3] = fmaf(p3, vv.w, o[3][3]);
        }
    }

    #pragma unroll
    for (int i = 0; i < 4; i++) {
        float inv = (lrow[i] > 0.f) ? (1.f / lrow[i]) : 0.f;
        int qg = q0 + 4 * ty + i;
        float4 v;
        v.x = o[i][0] * inv; v.y = o[i][1] * inv;
        v.z = o[i][2] * inv; v.w = o[i][3] * inv;
        *(float4*)(out + ((size_t)(b * Sc) + qg) * Dc + h * HDc + 4 * tx) = v;
    }
}

// ---------------------------------------------------------------------------
// Launcher
// ---------------------------------------------------------------------------
extern "C" void kernel_launch(void* const* d_in, const int* in_sizes, int n_in,
                              void* d_out, int out_size)
{
    const float*         inp   = (const float*)d_in[0];
    const unsigned char* mask  = (const unsigned char*)d_in[1];
    const int*           relm  = (const int*)d_in[2];
    const float*         qkv_w = (const float*)d_in[3];
    const float*         relA  = (const float*)d_in[4];
    const float*         o_w   = (const float*)d_in[5];
    const float*         w1    = (const float*)d_in[6];
    const float*         b1    = (const float*)d_in[7];
    const float*         w2    = (const float*)d_in[8];
    const float*         b2    = (const float*)d_in[9];
    const float*         ln1g  = (const float*)d_in[10];
    const float*         ln1b  = (const float*)d_in[11];
    const float*         ln2g  = (const float*)d_in[12];
    const float*         ln2b  = (const float*)d_in[13];
    float* out = (float*)d_out;

    float *p_xln, *p_qkv, *p_att, *p_res1, *p_hln, *p_ff;
    cudaGetSymbolAddress((void**)&p_xln,  g_xln);
    cudaGetSymbolAddress((void**)&p_qkv,  g_qkv);
    cudaGetSymbolAddress((void**)&p_att,  g_att);
    cudaGetSymbolAddress((void**)&p_res1, g_res1);
    cudaGetSymbolAddress((void**)&p_hln,  g_hln);
    cudaGetSymbolAddress((void**)&p_ff,   g_ff);

    cudaFuncSetAttribute(attn_kernel, cudaFuncAttributeMaxDynamicSharedMemorySize,
                         ATT_SMEM_FLOATS * (int)sizeof(float));

    // 1. LN1
    ln_kernel<<<Mrows, 256>>>(inp, ln1g, ln1b, p_xln);

    // 2. QKV = xln @ qkv_w^T       [2048 x 2304], grid 18x32=576
    sgemm_x2<<<dim3(3 * Dc / 128, Mrows / 64), 128>>>(
        p_xln, qkv_w, nullptr, nullptr, p_qkv, Mrows, 3 * Dc, Dc, 0);

    // 3. Fused attention
    attn_kernel<<<dim3(Sc / 64, Bc * Hc), 256, ATT_SMEM_FLOATS * sizeof(float)>>>(
        p_qkv, relm, mask, relA, p_att);

    // 4. res1 = inp + att @ o_w^T  [2048 x 768], grid 6x32=192
    sgemm_x2<<<dim3(Dc / 128, Mrows / 64), 128>>>(
        p_att, o_w, nullptr, inp, p_res1, Mrows, Dc, Dc, 0);

    // 5. LN2
    ln_kernel<<<Mrows, 256>>>(p_res1, ln2g, ln2b, p_hln);

    // 6. ff = relu(hln @ w1^T + b1)  [2048 x 3072], grid 24x32=768
    sgemm_x2<<<dim3(DFFc / 128, Mrows / 64), 128>>>(
        p_hln, w1, b1, nullptr, p_ff, Mrows, DFFc, Dc, 1);

    // 7. out = res1 + ff @ w2^T + b2  [2048 x 768], grid 6x32=192
    sgemm_x2<<<dim3(Dc / 128, Mrows / 64), 128>>>(
        p_ff, w2, b2, p_res1, out, Mrows, Dc, DFFc, 0);
}